// round 2
// baseline (speedup 1.0000x reference)
#include <cuda_runtime.h>

// Memory_9835475108444: Hebbian fast-weight scan, low-rank reformulation.
//   A_t = (1-d)^t A_0 + sum_{s<t} (1-d)^{t-1-s} x_s p_s^T
// Kernel 1 streams A_0 once (max MLP, zero fast path) producing g_t = A_0 @ x_t.
// Kernel 2 runs the rank-16 recurrence per batch in shared memory.

#define BB 256
#define MM 256
#define TT 16
#define NCHUNK 4                 // CTAs per batch in kernel 1
#define ROWS_PER_CHUNK (MM / NCHUNK)   // 64

// scratch: g[b][t][row], t in [0,16] (16 = x_query)
__device__ float g_scratch[BB * (TT + 1) * MM];

__device__ __forceinline__ unsigned f4_bits_or(float4 v) {
    return __float_as_uint(v.x) | __float_as_uint(v.y) |
           __float_as_uint(v.z) | __float_as_uint(v.w);
}

// ---------------- kernel 1: stream A_0, compute g (zero fast path) -------------
__global__ __launch_bounds__(MM) void scan_gemv_kernel(
    const float* __restrict__ A0,     // (B, M, M)
    const float* __restrict__ xs,     // (T, B, M)
    const float* __restrict__ xq)     // (B, M)
{
    __shared__ float sx[TT + 1][MM + 1];

    const int c   = blockIdx.x;               // chunk 0..3
    const int b   = blockIdx.y;               // batch
    const int tid = threadIdx.x;
    const int lane = tid & 31;
    const int wid  = tid >> 5;

    // This CTA's slice: rows [c*64, c*64+64) of A0[b] = 4096 float4.
    const float4* __restrict__ p =
        reinterpret_cast<const float4*>(A0) + (size_t)b * (MM * MM / 4)
                                            + (size_t)c * (ROWS_PER_CHUNK * MM / 4);

    // Fully independent streaming loads: 16 LDG.128 per thread, no consumption
    // between loads -> maximal MLP. OR of raw bits as the zero test
    // (-0.0 counts as nonzero -> general path; still correct, never hit here).
    unsigned nz = 0u;
    #pragma unroll
    for (int k = 0; k < 16; k++) {
        float4 v = p[tid + k * MM];
        nz |= f4_bits_or(v);
    }

    float* __restrict__ gb = g_scratch + (size_t)b * (TT + 1) * MM;

    if (!__syncthreads_or((int)(nz != 0u))) {
        // Entire chunk of A_0 is zero (dataset path): g contributions are 0.
        #pragma unroll
        for (int i = tid; i < (TT + 1) * ROWS_PER_CHUNK; i += MM) {
            int t = i / ROWS_PER_CHUNK;
            int r = c * ROWS_PER_CHUNK + (i % ROWS_PER_CHUNK);
            gb[t * MM + r] = 0.0f;
        }
        return;
    }

    // General path (arbitrary A_0): chunk is hot in L1; warp-per-row dots.
    #pragma unroll
    for (int t = 0; t < TT; t++)
        sx[t][tid] = xs[(size_t)t * BB * MM + (size_t)b * MM + tid];
    sx[TT][tid] = xq[(size_t)b * MM + tid];
    __syncthreads();

    #pragma unroll
    for (int rr = 0; rr < ROWS_PER_CHUNK / 8; rr++) {   // 8 rows per warp
        const int row_local = wid * (ROWS_PER_CHUNK / 8) + rr;
        const float4* ar = p + row_local * (MM / 4);
        float4 a0 = ar[lane];
        float4 a1 = ar[lane + 32];

        float acc[TT + 1];
        #pragma unroll
        for (int t = 0; t <= TT; t++) acc[t] = 0.f;
        const int j0 = lane * 4;
        const int j1 = (lane + 32) * 4;
        #pragma unroll
        for (int t = 0; t <= TT; t++) {
            acc[t] += a0.x * sx[t][j0]     + a0.y * sx[t][j0 + 1]
                    + a0.z * sx[t][j0 + 2] + a0.w * sx[t][j0 + 3];
            acc[t] += a1.x * sx[t][j1]     + a1.y * sx[t][j1 + 1]
                    + a1.z * sx[t][j1 + 2] + a1.w * sx[t][j1 + 3];
        }
        #pragma unroll
        for (int t = 0; t <= TT; t++) {
            #pragma unroll
            for (int off = 16; off > 0; off >>= 1)
                acc[t] += __shfl_down_sync(0xffffffffu, acc[t], off);
        }
        if (lane == 0) {
            int row = c * ROWS_PER_CHUNK + row_local;
            #pragma unroll
            for (int t = 0; t <= TT; t++) gb[t * MM + row] = acc[t];
        }
    }
}

// ---------------- kernel 2: rank-16 recurrence per batch ----------------------
__global__ __launch_bounds__(MM) void recurrence_kernel(
    const float* __restrict__ xs,
    const float* __restrict__ xq,
    const float* __restrict__ pdecay,
    const float* __restrict__ plearn,
    const float* __restrict__ plearn2,
    float* __restrict__ out)
{
    __shared__ float sx[TT + 1][MM + 1];
    __shared__ float U[TT + 1][MM + 1];   // g_t -> overwritten in place by p_t
    __shared__ float sdot[TT];

    const int b    = blockIdx.x;
    const int tid  = threadIdx.x;
    const int lane = tid & 31;
    const int wid  = tid >> 5;

    const float* __restrict__ gb = g_scratch + (size_t)b * (TT + 1) * MM;

    #pragma unroll
    for (int t = 0; t < TT; t++)
        sx[t][tid] = xs[(size_t)t * BB * MM + (size_t)b * MM + tid];
    sx[TT][tid] = xq[(size_t)b * MM + tid];
    #pragma unroll
    for (int t = 0; t <= TT; t++)
        U[t][tid] = gb[t * MM + tid];
    __syncthreads();

    const float decay  = pdecay[0];
    const float learn  = plearn[0];
    const float learn2 = plearn2[0];
    const float omd    = 1.0f - decay;

    float pw = 1.0f;  // (1-d)^t
    for (int t = 0; t < TT; t++) {
        for (int s = wid; s < t; s += 8) {
            float part = 0.f;
            #pragma unroll
            for (int e = 0; e < MM / 32; e++) {
                int j = lane + 32 * e;
                part += U[s][j] * sx[t][j];
            }
            #pragma unroll
            for (int off = 16; off > 0; off >>= 1)
                part += __shfl_down_sync(0xffffffffu, part, off);
            if (lane == 0) sdot[s] = part;
        }
        __syncthreads();

        float ax = pw * U[t][tid];
        float cc = 1.0f;
        for (int s = t - 1; s >= 0; s--) {
            ax += cc * sdot[s] * sx[s][tid];
            cc *= omd;
        }
        float v = learn2 * sx[t][tid] + ax;
        v = fminf(fmaxf(v, 0.f), 6.f);
        U[t][tid] = learn * v;
        pw *= omd;
        __syncthreads();
    }

    for (int s = wid; s < TT; s += 8) {
        float part = 0.f;
        #pragma unroll
        for (int e = 0; e < MM / 32; e++) {
            int j = lane + 32 * e;
            part += U[s][j] * sx[TT][j];
        }
        #pragma unroll
        for (int off = 16; off > 0; off >>= 1)
            part += __shfl_down_sync(0xffffffffu, part, off);
        if (lane == 0) sdot[s] = part;
    }
    __syncthreads();

    float ax = pw * U[TT][tid];
    float cc = 1.0f;
    for (int s = TT - 1; s >= 0; s--) {
        ax += cc * sdot[s] * sx[s][tid];
        cc *= omd;
    }
    out[(size_t)b * MM + tid] = fminf(fmaxf(ax, 0.f), 6.f);
}

extern "C" void kernel_launch(void* const* d_in, const int* in_sizes, int n_in,
                              void* d_out, int out_size) {
    const float* A0     = (const float*)d_in[0];
    const float* xs     = (const float*)d_in[1];
    const float* xq     = (const float*)d_in[2];
    const float* decay  = (const float*)d_in[3];
    const float* learn  = (const float*)d_in[4];
    const float* learn2 = (const float*)d_in[5];
    float* out = (float*)d_out;

    dim3 g1(NCHUNK, BB);
    scan_gemv_kernel<<<g1, MM>>>(A0, xs, xq);
    recurrence_kernel<<<BB, MM>>>(xs, xq, decay, learn, learn2, out);
}

// round 3
// speedup vs baseline: 1.0111x; 1.0111x over previous
#include <cuda_runtime.h>

// Memory_9835475108444: Hebbian fast-weight scan, fused single kernel.
//   A_t = (1-d)^t A_0 + sum_{s<t} (1-d)^{t-1-s} x_s p_s^T      (exact, rank-16)
// Per CTA (one batch): stream A_0[b] once with max MLP (bitwise-OR zero test),
// then a register-resident rank-16 recurrence with ONE barrier per step.

#define BB 256
#define MM 256
#define TT 16

__device__ __forceinline__ unsigned f4or(float4 v) {
    return __float_as_uint(v.x) | __float_as_uint(v.y) |
           __float_as_uint(v.z) | __float_as_uint(v.w);
}

__global__ __launch_bounds__(MM) void memory_fused_kernel(
    const float* __restrict__ A0,     // (B, M, M)
    const float* __restrict__ xs,     // (T, B, M)
    const float* __restrict__ xq,     // (B, M)
    const float* __restrict__ pdecay,
    const float* __restrict__ plearn,
    const float* __restrict__ plearn2,
    float* __restrict__ out)          // (B, M)
{
    __shared__ float wpart[2][TT + 1][8];   // double-buffered warp partials
    __shared__ float sx[TT + 1][MM + 1];    // general (nonzero-A) path only
    __shared__ float gsm[TT + 1][MM + 1];   // general path only

    const int b    = blockIdx.x;
    const int tid  = threadIdx.x;
    const int lane = tid & 31;
    const int wid  = tid >> 5;

    // ---- register-resident x vectors: thread tid owns element i = tid ----
    float xr[TT + 1];
    #pragma unroll
    for (int t = 0; t < TT; t++)
        xr[t] = xs[(size_t)t * BB * MM + (size_t)b * MM + tid];
    xr[TT] = xq[(size_t)b * MM + tid];

    // ---- stream A0[b] (256 KB) with fully independent loads, OR-fold ----
    const float4* __restrict__ p =
        reinterpret_cast<const float4*>(A0) + (size_t)b * (MM * MM / 4);
    unsigned nz = 0u;
    #pragma unroll
    for (int k = 0; k < 64; k++)
        nz |= f4or(p[tid + k * MM]);        // 64 independent LDG.128 per thread

    float gr[TT + 1];                       // g_t[i] = (A0 @ x_t)[i], i = tid
    if (__syncthreads_or((int)(nz != 0u))) {
        // ---- general path (arbitrary A0): warp-per-row dots, A from L2 ----
        #pragma unroll
        for (int t = 0; t <= TT; t++) sx[t][tid] = xr[t];
        __syncthreads();
        for (int row = wid; row < MM; row += 8) {
            const float4* ar = p + row * (MM / 4);
            float4 a0 = ar[lane];
            float4 a1 = ar[lane + 32];
            float acc[TT + 1];
            #pragma unroll
            for (int t = 0; t <= TT; t++) acc[t] = 0.f;
            const int j0 = lane * 4, j1 = (lane + 32) * 4;
            #pragma unroll
            for (int t = 0; t <= TT; t++) {
                acc[t] += a0.x * sx[t][j0]     + a0.y * sx[t][j0 + 1]
                        + a0.z * sx[t][j0 + 2] + a0.w * sx[t][j0 + 3];
                acc[t] += a1.x * sx[t][j1]     + a1.y * sx[t][j1 + 1]
                        + a1.z * sx[t][j1 + 2] + a1.w * sx[t][j1 + 3];
            }
            #pragma unroll
            for (int t = 0; t <= TT; t++) {
                #pragma unroll
                for (int off = 16; off > 0; off >>= 1)
                    acc[t] += __shfl_down_sync(0xffffffffu, acc[t], off);
            }
            if (lane == 0) {
                #pragma unroll
                for (int t = 0; t <= TT; t++) gsm[t][row] = acc[t];
            }
        }
        __syncthreads();
        #pragma unroll
        for (int t = 0; t <= TT; t++) gr[t] = gsm[t][tid];
    } else {
        // zero A0 (dataset path): all g contributions vanish
        #pragma unroll
        for (int t = 0; t <= TT; t++) gr[t] = 0.f;
    }

    // ---- rank-16 recurrence, register resident, 1 barrier/step ----
    const float decay  = pdecay[0];
    const float learn  = plearn[0];
    const float learn2 = plearn2[0];
    const float omd    = 1.0f - decay;

    float pr[TT];
    float pw = 1.0f;                        // (1-d)^t

    #pragma unroll
    for (int t = 0; t < TT; t++) {
        // phase A: warp partials of q_{t,s} = p_s . x_t (independent trees)
        #pragma unroll
        for (int s = 0; s < t; s++) {
            float v = pr[s] * xr[t];
            #pragma unroll
            for (int off = 16; off > 0; off >>= 1)
                v += __shfl_down_sync(0xffffffffu, v, off);
            if (lane == 0) wpart[t & 1][s][wid] = v;
        }
        if (t > 0) __syncthreads();

        // phase B: finish dots from 8 broadcast partials, axpy in registers
        float ax = pw * gr[t];
        float cc = 1.0f;
        #pragma unroll
        for (int s = t - 1; s >= 0; s--) {
            float4 lo = *reinterpret_cast<const float4*>(&wpart[t & 1][s][0]);
            float4 hi = *reinterpret_cast<const float4*>(&wpart[t & 1][s][4]);
            float q = ((lo.x + lo.y) + (lo.z + lo.w)) +
                      ((hi.x + hi.y) + (hi.z + hi.w));
            ax += cc * q * xr[s];
            cc *= omd;
        }
        float v = learn2 * xr[t] + ax;
        pr[t] = learn * fminf(fmaxf(v, 0.f), 6.f);
        pw *= omd;
    }

    // ---- epilogue: out = relu6(A_T @ x_query) via same machinery ----
    #pragma unroll
    for (int s = 0; s < TT; s++) {
        float v = pr[s] * xr[TT];
        #pragma unroll
        for (int off = 16; off > 0; off >>= 1)
            v += __shfl_down_sync(0xffffffffu, v, off);
        if (lane == 0) wpart[0][s][wid] = v;
    }
    __syncthreads();

    float ax = pw * gr[TT];                 // pw == (1-d)^T
    float cc = 1.0f;
    #pragma unroll
    for (int s = TT - 1; s >= 0; s--) {
        float4 lo = *reinterpret_cast<const float4*>(&wpart[0][s][0]);
        float4 hi = *reinterpret_cast<const float4*>(&wpart[0][s][4]);
        float q = ((lo.x + lo.y) + (lo.z + lo.w)) +
                  ((hi.x + hi.y) + (hi.z + hi.w));
        ax += cc * q * xr[s];
        cc *= omd;
    }
    out[(size_t)b * MM + tid] = fminf(fmaxf(ax, 0.f), 6.f);
}

extern "C" void kernel_launch(void* const* d_in, const int* in_sizes, int n_in,
                              void* d_out, int out_size) {
    const float* A0     = (const float*)d_in[0];
    const float* xs     = (const float*)d_in[1];
    const float* xq     = (const float*)d_in[2];
    const float* decay  = (const float*)d_in[3];
    const float* learn  = (const float*)d_in[4];
    const float* learn2 = (const float*)d_in[5];
    float* out = (float*)d_out;

    memory_fused_kernel<<<BB, MM>>>(A0, xs, xq, decay, learn, learn2, out);
}